// round 2
// baseline (speedup 1.0000x reference)
#include <cuda_runtime.h>
#include <math.h>

#define B_   16
#define T_   512
#define F_   17
#define K_   20
#define FEAT (F_*K_)        // 340
#define FL   30
#define NFR  (T_ - FL + 1)  // 483
#define TB   16
#define EPSF 1e-12f

// Scratch: ping-pong activation buffers for both towers stacked as 32 "batches".
// Layout [bb][t][f][k], k contiguous -> feature index f*K+k matches reshape(B,T,F*K).
__device__ float g_bufA[2 * B_ * T_ * F_ * K_];
__device__ float g_bufB[2 * B_ * T_ * F_ * K_];

// ---------------------------------------------------------------------------
// Conv 3x3 SAME + bias + ReLU. NHWC activations, HWIO weights.
// CTA = (t-block of TB rows) x (one of 32 tower-batches). 256 threads.
// Each thread computes up to 2 spatial positions x all 20 output channels,
// reusing the 20 weight values across both positions.
// SRC: 0 = g_bufA, 1 = g_bufB (ignored when FIRST). DST likewise.
// ---------------------------------------------------------------------------
template<int CIN, bool FIRST, int SRC, int DST>
__global__ void __launch_bounds__(256) conv_kernel(
    const float* __restrict__ in0, const float* __restrict__ in1,
    const float* __restrict__ w,   const float* __restrict__ bias)
{
    __shared__ float tile[(TB + 2) * (F_ + 2) * CIN];  // zero-padded halo
    __shared__ float ws[9 * CIN * K_];
    __shared__ float bs[K_];

    const int tid = threadIdx.x;
    const int t0  = blockIdx.x * TB;
    const int bb  = blockIdx.y;   // 0..31 (0..15 = S tower, 16..31 = X tower)

    for (int i = tid; i < 9 * CIN * K_; i += 256) ws[i] = w[i];
    if (tid < K_) bs[tid] = bias[tid];

    const float* src;
    if (FIRST) {
        src = (bb < B_) ? (in0 + (size_t)bb * T_ * F_)
                        : (in1 + (size_t)(bb - B_) * T_ * F_);
    } else {
        const float* base = (SRC == 0) ? g_bufA : g_bufB;
        src = base + (size_t)bb * T_ * F_ * CIN;
    }
    float* dst = ((DST == 0) ? g_bufA : g_bufB);

    const int tileN = (TB + 2) * (F_ + 2) * CIN;
    for (int i = tid; i < tileN; i += 256) {
        int cin  = i % CIN;
        int rest = i / CIN;
        int ff   = rest % (F_ + 2);
        int tt   = rest / (F_ + 2);
        int t = t0 - 1 + tt;
        int f = ff - 1;
        float v = 0.f;
        if (t >= 0 && t < T_ && f >= 0 && f < F_)
            v = src[((size_t)t * F_ + f) * CIN + cin];
        tile[i] = v;
    }
    __syncthreads();

    float acc0[K_], acc1[K_];
#pragma unroll
    for (int k = 0; k < K_; k++) { acc0[k] = bs[k]; acc1[k] = bs[k]; }

    const int pos0 = tid;             // TB*F_ = 272 positions, 256 threads
    const int pos1 = tid + 256;
    const int lt0 = pos0 / F_, lf0 = pos0 % F_;
    const int lt1 = pos1 / F_, lf1 = pos1 % F_;
    const bool has1 = (pos1 < TB * F_);

    for (int cin = 0; cin < CIN; cin++) {
#pragma unroll
        for (int dt = 0; dt < 3; dt++) {
#pragma unroll
            for (int df = 0; df < 3; df++) {
                const float* wp = &ws[((dt * 3 + df) * CIN + cin) * K_];
                float i0 = tile[((lt0 + dt) * (F_ + 2) + lf0 + df) * CIN + cin];
                float i1 = has1 ? tile[((lt1 + dt) * (F_ + 2) + lf1 + df) * CIN + cin] : 0.f;
#pragma unroll
                for (int k = 0; k < K_; k++) {
                    float wv = wp[k];
                    acc0[k] = fmaf(i0, wv, acc0[k]);
                    acc1[k] = fmaf(i1, wv, acc1[k]);
                }
            }
        }
    }

    {
        int t = t0 + lt0;
        float* o = dst + (((size_t)bb * T_ + t) * F_ + lf0) * K_;
#pragma unroll
        for (int k = 0; k < K_; k++) o[k] = fmaxf(acc0[k], 0.f);
    }
    if (has1) {
        int t = t0 + lt1;
        float* o = dst + (((size_t)bb * T_ + t) * F_ + lf1) * K_;
#pragma unroll
        for (int k = 0; k < K_; k++) o[k] = fmaxf(acc1[k], 0.f);
    }
}

// ---------------------------------------------------------------------------
// Per-frame double-normalized cross-correlation. Final conv output is in g_bufA.
// One CTA per (frame, batch). Each frame of each tower is one CONTIGUOUS
// 10200-float segment (rows contiguous in t).
// Static smem only (<= 48KB): stage the S frame; for X keep only per-column
// mu/inv (stats pass reads X from global, dot pass reads it again — coalesced,
// L2-resident).
// Row normalization is algebraic: per row t, warp-reduce {Su,Sv,Su2,Sv2,Suv};
//   contribution = (Suv - n*mu_u*mu_v)/((sig_u+eps)*(sig_v+eps)).
// ---------------------------------------------------------------------------
__global__ void __launch_bounds__(256) corr_kernel(float* __restrict__ out)
{
    __shared__ float sS[FL * FEAT];        // 40800 B
    __shared__ float muX[FEAT], invX[FEAT];
    __shared__ float red[8];

    const int fr  = blockIdx.x;   // 0..482
    const int b   = blockIdx.y;   // 0..15
    const int tid = threadIdx.x;

    const float* S = g_bufA + ((size_t)b * T_ + fr) * FEAT;
    const float* X = g_bufA + ((size_t)(b + B_) * T_ + fr) * FEAT;

    for (int i = tid; i < FL * FEAT; i += 256) sS[i] = S[i];
    __syncthreads();

    // Column normalize S (in smem) and compute X column stats (from global).
    for (int col = tid; col < FEAT; col += 256) {
        float s = 0.f, s2 = 0.f;
#pragma unroll 6
        for (int t = 0; t < FL; t++) {
            float v = sS[t * FEAT + col];
            s += v; s2 += v * v;
        }
        float mu  = s * (1.0f / FL);
        float var = fmaxf(s2 - (float)FL * mu * mu, 0.f);
        float inv = 1.f / (sqrtf(var) + EPSF);
#pragma unroll 6
        for (int t = 0; t < FL; t++)
            sS[t * FEAT + col] = (sS[t * FEAT + col] - mu) * inv;

        s = 0.f; s2 = 0.f;
#pragma unroll 6
        for (int t = 0; t < FL; t++) {
            float v = X[t * FEAT + col];     // coalesced across threads
            s += v; s2 += v * v;
        }
        mu  = s * (1.0f / FL);
        var = fmaxf(s2 - (float)FL * mu * mu, 0.f);
        muX[col]  = mu;
        invX[col] = 1.f / (sqrtf(var) + EPSF);
    }
    __syncthreads();

    // Rows: one warp per row (8 warps round-robin over 30 rows).
    const int warp = tid >> 5, lane = tid & 31;
    float acc = 0.f;
    for (int t = warp; t < FL; t += 8) {
        float aU = 0.f, aV = 0.f, a2U = 0.f, a2V = 0.f, aUV = 0.f;
        for (int c = lane; c < FEAT; c += 32) {
            float u = sS[t * FEAT + c];
            float v = (X[t * FEAT + c] - muX[c]) * invX[c];
            aU += u; aV += v; a2U += u * u; a2V += v * v; aUV += u * v;
        }
#pragma unroll
        for (int o = 16; o > 0; o >>= 1) {
            aU  += __shfl_down_sync(0xffffffffu, aU,  o);
            aV  += __shfl_down_sync(0xffffffffu, aV,  o);
            a2U += __shfl_down_sync(0xffffffffu, a2U, o);
            a2V += __shfl_down_sync(0xffffffffu, a2V, o);
            aUV += __shfl_down_sync(0xffffffffu, aUV, o);
        }
        if (lane == 0) {
            float muU = aU * (1.0f / FEAT), muV = aV * (1.0f / FEAT);
            float sgU = sqrtf(fmaxf(a2U - (float)FEAT * muU * muU, 0.f));
            float sgV = sqrtf(fmaxf(a2V - (float)FEAT * muV * muV, 0.f));
            float dot = aUV - (float)FEAT * muU * muV;
            acc += dot / ((sgU + EPSF) * (sgV + EPSF));
        }
    }
    if (lane == 0) red[warp] = acc;
    __syncthreads();
    if (tid == 0) {
        float tot = 0.f;
#pragma unroll
        for (int i = 0; i < 8; i++) tot += red[i];
        atomicAdd(&out[b], tot * (1.0f / ((float)FL * (float)NFR)));
    }
}

__global__ void zero_out(float* out, int n)
{
    int i = blockIdx.x * blockDim.x + threadIdx.x;
    if (i < n) out[i] = 0.f;
}

extern "C" void kernel_launch(void* const* d_in, const int* in_sizes, int n_in,
                              void* d_out, int out_size)
{
    const float* s  = (const float*)d_in[0];
    const float* x  = (const float*)d_in[1];
    const float* w0 = (const float*)d_in[2];
    const float* b0 = (const float*)d_in[3];
    const float* w1 = (const float*)d_in[4];
    const float* b1 = (const float*)d_in[5];
    const float* w2 = (const float*)d_in[6];
    const float* b2 = (const float*)d_in[7];
    float* out = (float*)d_out;

    zero_out<<<1, 32>>>(out, out_size);

    dim3 cgrid(T_ / TB, 2 * B_);
    conv_kernel<1,  true,  0, 0><<<cgrid, 256>>>(s, x, w0, b0);            // -> bufA
    conv_kernel<K_, false, 0, 1><<<cgrid, 256>>>(nullptr, nullptr, w1, b1); // A -> B
    conv_kernel<K_, false, 1, 0><<<cgrid, 256>>>(nullptr, nullptr, w2, b2); // B -> A

    dim3 ggrid(NFR, B_);
    corr_kernel<<<ggrid, 256>>>(out);
}

// round 5
// speedup vs baseline: 1.0813x; 1.0813x over previous
#include <cuda_runtime.h>
#include <math.h>

#define B_   16
#define T_   512
#define F_   17
#define K_   20
#define FEAT (F_*K_)        // 340
#define FL   30
#define NFR  (T_ - FL + 1)  // 483
#define TB   16
#define EPSF 1e-12f

// Scratch: ping-pong activation buffers for both towers stacked as 32 "batches".
// Layout [bb][t][f][k], k contiguous -> feature index f*K+k matches reshape(B,T,F*K).
__device__ float g_bufA[2 * B_ * T_ * F_ * K_];
__device__ float g_bufB[2 * B_ * T_ * F_ * K_];

// ---------------------------------------------------------------------------
// Conv 3x3 SAME + bias + ReLU. NHWC activations, HWIO weights.
// CTA = (t-block of TB rows) x (one of 32 tower-batches). 256 threads.
// Each thread computes up to 2 spatial positions x all 20 output channels.
// L1-wavefront fixes vs round 2:
//   * tile inner stride padded to CINP=21 (gcd(21,32)=1) -> conflict-free LDS
//   * weights read as float4 (5x LDS.128 broadcast instead of 20x LDS.32)
// ---------------------------------------------------------------------------
template<int CIN, bool FIRST, int SRC, int DST>
__global__ void __launch_bounds__(256) conv_kernel(
    const float* __restrict__ in0, const float* __restrict__ in1,
    const float* __restrict__ w,   const float* __restrict__ bias)
{
    constexpr int CINP = (CIN % 2 == 0) ? CIN + 1 : CIN;   // 21 for 20, 1 for 1

    __shared__ float tile[(TB + 2) * (F_ + 2) * CINP];     // zero-padded halo
    __shared__ __align__(16) float ws[9 * CIN * K_];
    __shared__ float bs[K_];

    const int tid = threadIdx.x;
    const int t0  = blockIdx.x * TB;
    const int bb  = blockIdx.y;   // 0..31 (0..15 = S tower, 16..31 = X tower)

    for (int i = tid; i < 9 * CIN * K_; i += 256) ws[i] = w[i];
    if (tid < K_) bs[tid] = bias[tid];

    const float* src;
    if (FIRST) {
        src = (bb < B_) ? (in0 + (size_t)bb * T_ * F_)
                        : (in1 + (size_t)(bb - B_) * T_ * F_);
    } else {
        const float* base = (SRC == 0) ? g_bufA : g_bufB;
        src = base + (size_t)bb * T_ * F_ * CIN;
    }
    float* dst = ((DST == 0) ? g_bufA : g_bufB);

    const int tileN = (TB + 2) * (F_ + 2) * CIN;   // logical elements
    for (int i = tid; i < tileN; i += 256) {
        int cin  = i % CIN;
        int rest = i / CIN;
        int ff   = rest % (F_ + 2);
        int tt   = rest / (F_ + 2);
        int t = t0 - 1 + tt;
        int f = ff - 1;
        float v = 0.f;
        if (t >= 0 && t < T_ && f >= 0 && f < F_)
            v = src[((size_t)t * F_ + f) * CIN + cin];
        tile[(tt * (F_ + 2) + ff) * CINP + cin] = v;
    }
    __syncthreads();

    float acc0[K_], acc1[K_];
#pragma unroll
    for (int k = 0; k < K_; k++) { acc0[k] = bs[k]; acc1[k] = bs[k]; }

    const int pos0 = tid;             // TB*F_ = 272 positions, 256 threads
    const bool has1 = (tid + 256 < TB * F_);
    const int pos1 = has1 ? (tid + 256) : 0;     // clamp keeps smem idx in-bounds
    const int lt0 = pos0 / F_, lf0 = pos0 % F_;
    const int lt1 = pos1 / F_, lf1 = pos1 % F_;

    for (int cin = 0; cin < CIN; cin++) {
#pragma unroll
        for (int dt = 0; dt < 3; dt++) {
#pragma unroll
            for (int df = 0; df < 3; df++) {
                const float4* wp4 = reinterpret_cast<const float4*>(
                    &ws[((dt * 3 + df) * CIN + cin) * K_]);   // 80B-aligned group
                float i0 = tile[((lt0 + dt) * (F_ + 2) + lf0 + df) * CINP + cin];
                float i1 = tile[((lt1 + dt) * (F_ + 2) + lf1 + df) * CINP + cin];
#pragma unroll
                for (int q = 0; q < 5; q++) {
                    float4 wv = wp4[q];
                    acc0[4*q+0] = fmaf(i0, wv.x, acc0[4*q+0]);
                    acc0[4*q+1] = fmaf(i0, wv.y, acc0[4*q+1]);
                    acc0[4*q+2] = fmaf(i0, wv.z, acc0[4*q+2]);
                    acc0[4*q+3] = fmaf(i0, wv.w, acc0[4*q+3]);
                    acc1[4*q+0] = fmaf(i1, wv.x, acc1[4*q+0]);
                    acc1[4*q+1] = fmaf(i1, wv.y, acc1[4*q+1]);
                    acc1[4*q+2] = fmaf(i1, wv.z, acc1[4*q+2]);
                    acc1[4*q+3] = fmaf(i1, wv.w, acc1[4*q+3]);
                }
            }
        }
    }

    {
        int t = t0 + lt0;
        float* o = dst + (((size_t)bb * T_ + t) * F_ + lf0) * K_;
#pragma unroll
        for (int k = 0; k < K_; k++) o[k] = fmaxf(acc0[k], 0.f);
    }
    if (has1) {
        int t = t0 + lt1;
        float* o = dst + (((size_t)bb * T_ + t) * F_ + lf1) * K_;
#pragma unroll
        for (int k = 0; k < K_; k++) o[k] = fmaxf(acc1[k], 0.f);
    }
}

// ---------------------------------------------------------------------------
// Per-frame double-normalized cross-correlation. Final conv output is in g_bufA.
// One CTA per (frame, batch). Each frame of each tower is one CONTIGUOUS
// 10200-float segment (rows contiguous in t).
// Static smem only (<= 48KB): stage the S frame; for X keep only per-column
// mu/inv (stats pass reads X from global, dot pass reads it again — coalesced,
// L2-resident).
// Row normalization is algebraic: per row t, warp-reduce {Su,Sv,Su2,Sv2,Suv};
//   contribution = (Suv - n*mu_u*mu_v)/((sig_u+eps)*(sig_v+eps)).
// ---------------------------------------------------------------------------
__global__ void __launch_bounds__(256) corr_kernel(float* __restrict__ out)
{
    __shared__ float sS[FL * FEAT];        // 40800 B
    __shared__ float muX[FEAT], invX[FEAT];
    __shared__ float red[8];

    const int fr  = blockIdx.x;   // 0..482
    const int b   = blockIdx.y;   // 0..15
    const int tid = threadIdx.x;

    const float* S = g_bufA + ((size_t)b * T_ + fr) * FEAT;
    const float* X = g_bufA + ((size_t)(b + B_) * T_ + fr) * FEAT;

    for (int i = tid; i < FL * FEAT; i += 256) sS[i] = S[i];
    __syncthreads();

    // Column normalize S (in smem) and compute X column stats (from global).
    for (int col = tid; col < FEAT; col += 256) {
        float s = 0.f, s2 = 0.f;
#pragma unroll 6
        for (int t = 0; t < FL; t++) {
            float v = sS[t * FEAT + col];
            s += v; s2 += v * v;
        }
        float mu  = s * (1.0f / FL);
        float var = fmaxf(s2 - (float)FL * mu * mu, 0.f);
        float inv = 1.f / (sqrtf(var) + EPSF);
#pragma unroll 6
        for (int t = 0; t < FL; t++)
            sS[t * FEAT + col] = (sS[t * FEAT + col] - mu) * inv;

        s = 0.f; s2 = 0.f;
#pragma unroll 6
        for (int t = 0; t < FL; t++) {
            float v = X[t * FEAT + col];     // coalesced across threads
            s += v; s2 += v * v;
        }
        mu  = s * (1.0f / FL);
        var = fmaxf(s2 - (float)FL * mu * mu, 0.f);
        muX[col]  = mu;
        invX[col] = 1.f / (sqrtf(var) + EPSF);
    }
    __syncthreads();

    // Rows: one warp per row (8 warps round-robin over 30 rows).
    const int warp = tid >> 5, lane = tid & 31;
    float acc = 0.f;
    for (int t = warp; t < FL; t += 8) {
        float aU = 0.f, aV = 0.f, a2U = 0.f, a2V = 0.f, aUV = 0.f;
        for (int c = lane; c < FEAT; c += 32) {
            float u = sS[t * FEAT + c];
            float v = (X[t * FEAT + c] - muX[c]) * invX[c];
            aU += u; aV += v; a2U += u * u; a2V += v * v; aUV += u * v;
        }
#pragma unroll
        for (int o = 16; o > 0; o >>= 1) {
            aU  += __shfl_down_sync(0xffffffffu, aU,  o);
            aV  += __shfl_down_sync(0xffffffffu, aV,  o);
            a2U += __shfl_down_sync(0xffffffffu, a2U, o);
            a2V += __shfl_down_sync(0xffffffffu, a2V, o);
            aUV += __shfl_down_sync(0xffffffffu, aUV, o);
        }
        if (lane == 0) {
            float muU = aU * (1.0f / FEAT), muV = aV * (1.0f / FEAT);
            float sgU = sqrtf(fmaxf(a2U - (float)FEAT * muU * muU, 0.f));
            float sgV = sqrtf(fmaxf(a2V - (float)FEAT * muV * muV, 0.f));
            float dot = aUV - (float)FEAT * muU * muV;
            acc += dot / ((sgU + EPSF) * (sgV + EPSF));
        }
    }
    if (lane == 0) red[warp] = acc;
    __syncthreads();
    if (tid == 0) {
        float tot = 0.f;
#pragma unroll
        for (int i = 0; i < 8; i++) tot += red[i];
        atomicAdd(&out[b], tot * (1.0f / ((float)FL * (float)NFR)));
    }
}

__global__ void zero_out(float* out, int n)
{
    int i = blockIdx.x * blockDim.x + threadIdx.x;
    if (i < n) out[i] = 0.f;
}

extern "C" void kernel_launch(void* const* d_in, const int* in_sizes, int n_in,
                              void* d_out, int out_size)
{
    const float* s  = (const float*)d_in[0];
    const float* x  = (const float*)d_in[1];
    const float* w0 = (const float*)d_in[2];
    const float* b0 = (const float*)d_in[3];
    const float* w1 = (const float*)d_in[4];
    const float* b1 = (const float*)d_in[5];
    const float* w2 = (const float*)d_in[6];
    const float* b2 = (const float*)d_in[7];
    float* out = (float*)d_out;

    zero_out<<<1, 32>>>(out, out_size);

    dim3 cgrid(T_ / TB, 2 * B_);
    conv_kernel<1,  true,  0, 0><<<cgrid, 256>>>(s, x, w0, b0);             // -> bufA
    conv_kernel<K_, false, 0, 1><<<cgrid, 256>>>(nullptr, nullptr, w1, b1); // A -> B
    conv_kernel<K_, false, 1, 0><<<cgrid, 256>>>(nullptr, nullptr, w2, b2); // B -> A

    dim3 ggrid(NFR, B_);
    corr_kernel<<<ggrid, 256>>>(out);
}

// round 6
// speedup vs baseline: 1.1463x; 1.0602x over previous
#include <cuda_runtime.h>
#include <math.h>

#define B_   16
#define T_   512
#define F_   17
#define K_   20
#define FEAT (F_*K_)        // 340
#define FL   30
#define NFR  (T_ - FL + 1)  // 483
#define TB   16
#define EPSF 1e-12f

// Scratch: ping-pong activation buffers for both towers stacked as 32 "batches".
__device__ float g_bufA[2 * B_ * T_ * F_ * K_];
__device__ float g_bufB[2 * B_ * T_ * F_ * K_];

// Weights/biases in constant memory: reads are warp-uniform -> LDC on the
// dedicated constant port, ZERO L1TEX wavefronts (the round-5 bottleneck).
__constant__ __align__(16) float CW0[9 * 1  * K_];   //   720 B
__constant__ __align__(16) float CW1[9 * K_ * K_];   // 14400 B
__constant__ __align__(16) float CW2[9 * K_ * K_];   // 14400 B
__constant__ float CB0[K_];
__constant__ float CB1[K_];
__constant__ float CB2[K_];

// ---------------------------------------------------------------------------
// Conv 3x3 SAME + bias + ReLU. NHWC activations, HWIO weights (in constant).
// CTA = (t-block of TB rows) x (one of 32 tower-batches). 256 threads.
// Each thread: up to 2 spatial positions x all 20 output channels.
// Per (cin,dt,df) step: 40 FFMA vs 2 conflict-free input LDS + 5 LDC.128.
// ---------------------------------------------------------------------------
template<int CIN, bool FIRST, int SRC, int DST, int LAYER>
__global__ void __launch_bounds__(256) conv_kernel(
    const float* __restrict__ in0, const float* __restrict__ in1)
{
    constexpr int CINP = (CIN % 2 == 0) ? CIN + 1 : CIN;   // 21 for 20, 1 for 1

    __shared__ float tile[(TB + 2) * (F_ + 2) * CINP];     // zero-padded halo

    const int tid = threadIdx.x;
    const int t0  = blockIdx.x * TB;
    const int bb  = blockIdx.y;   // 0..31 (0..15 = S tower, 16..31 = X tower)

    const float* src;
    if (FIRST) {
        src = (bb < B_) ? (in0 + (size_t)bb * T_ * F_)
                        : (in1 + (size_t)(bb - B_) * T_ * F_);
    } else {
        const float* base = (SRC == 0) ? g_bufA : g_bufB;
        src = base + (size_t)bb * T_ * F_ * CIN;
    }
    float* dst = ((DST == 0) ? g_bufA : g_bufB);

    const int tileN = (TB + 2) * (F_ + 2) * CIN;   // logical elements
    for (int i = tid; i < tileN; i += 256) {
        int cin  = i % CIN;
        int rest = i / CIN;
        int ff   = rest % (F_ + 2);
        int tt   = rest / (F_ + 2);
        int t = t0 - 1 + tt;
        int f = ff - 1;
        float v = 0.f;
        if (t >= 0 && t < T_ && f >= 0 && f < F_)
            v = src[((size_t)t * F_ + f) * CIN + cin];
        tile[(tt * (F_ + 2) + ff) * CINP + cin] = v;
    }
    __syncthreads();

    float acc0[K_], acc1[K_];
#pragma unroll
    for (int k = 0; k < K_; k++) {
        float bk;
        if constexpr (LAYER == 0) bk = CB0[k];
        else if constexpr (LAYER == 1) bk = CB1[k];
        else bk = CB2[k];
        acc0[k] = bk; acc1[k] = bk;
    }

    const int pos0 = tid;             // TB*F_ = 272 positions, 256 threads
    const bool has1 = (tid + 256 < TB * F_);
    const int pos1 = has1 ? (tid + 256) : 0;     // clamp keeps smem idx in-bounds
    const int lt0 = pos0 / F_, lf0 = pos0 % F_;
    const int lt1 = pos1 / F_, lf1 = pos1 % F_;

    for (int cin = 0; cin < CIN; cin++) {
#pragma unroll
        for (int dt = 0; dt < 3; dt++) {
#pragma unroll
            for (int df = 0; df < 3; df++) {
                const int wbase = ((dt * 3 + df) * CIN + cin) * K_;  // 80B-aligned
                float i0 = tile[((lt0 + dt) * (F_ + 2) + lf0 + df) * CINP + cin];
                float i1 = tile[((lt1 + dt) * (F_ + 2) + lf1 + df) * CINP + cin];
#pragma unroll
                for (int q = 0; q < 5; q++) {
                    float4 wv;
                    if constexpr (LAYER == 0)
                        wv = reinterpret_cast<const float4*>(CW0 + wbase)[q];
                    else if constexpr (LAYER == 1)
                        wv = reinterpret_cast<const float4*>(CW1 + wbase)[q];
                    else
                        wv = reinterpret_cast<const float4*>(CW2 + wbase)[q];
                    acc0[4*q+0] = fmaf(i0, wv.x, acc0[4*q+0]);
                    acc0[4*q+1] = fmaf(i0, wv.y, acc0[4*q+1]);
                    acc0[4*q+2] = fmaf(i0, wv.z, acc0[4*q+2]);
                    acc0[4*q+3] = fmaf(i0, wv.w, acc0[4*q+3]);
                    acc1[4*q+0] = fmaf(i1, wv.x, acc1[4*q+0]);
                    acc1[4*q+1] = fmaf(i1, wv.y, acc1[4*q+1]);
                    acc1[4*q+2] = fmaf(i1, wv.z, acc1[4*q+2]);
                    acc1[4*q+3] = fmaf(i1, wv.w, acc1[4*q+3]);
                }
            }
        }
    }

    {
        int t = t0 + lt0;
        float* o = dst + (((size_t)bb * T_ + t) * F_ + lf0) * K_;
#pragma unroll
        for (int k = 0; k < K_; k++) o[k] = fmaxf(acc0[k], 0.f);
    }
    if (has1) {
        int t = t0 + lt1;
        float* o = dst + (((size_t)bb * T_ + t) * F_ + lf1) * K_;
#pragma unroll
        for (int k = 0; k < K_; k++) o[k] = fmaxf(acc1[k], 0.f);
    }
}

// ---------------------------------------------------------------------------
// Per-frame double-normalized cross-correlation (unchanged from round 5).
// ---------------------------------------------------------------------------
__global__ void __launch_bounds__(256) corr_kernel(float* __restrict__ out)
{
    __shared__ float sS[FL * FEAT];        // 40800 B
    __shared__ float muX[FEAT], invX[FEAT];
    __shared__ float red[8];

    const int fr  = blockIdx.x;   // 0..482
    const int b   = blockIdx.y;   // 0..15
    const int tid = threadIdx.x;

    const float* S = g_bufA + ((size_t)b * T_ + fr) * FEAT;
    const float* X = g_bufA + ((size_t)(b + B_) * T_ + fr) * FEAT;

    for (int i = tid; i < FL * FEAT; i += 256) sS[i] = S[i];
    __syncthreads();

    for (int col = tid; col < FEAT; col += 256) {
        float s = 0.f, s2 = 0.f;
#pragma unroll 6
        for (int t = 0; t < FL; t++) {
            float v = sS[t * FEAT + col];
            s += v; s2 += v * v;
        }
        float mu  = s * (1.0f / FL);
        float var = fmaxf(s2 - (float)FL * mu * mu, 0.f);
        float inv = 1.f / (sqrtf(var) + EPSF);
#pragma unroll 6
        for (int t = 0; t < FL; t++)
            sS[t * FEAT + col] = (sS[t * FEAT + col] - mu) * inv;

        s = 0.f; s2 = 0.f;
#pragma unroll 6
        for (int t = 0; t < FL; t++) {
            float v = X[t * FEAT + col];     // coalesced across threads
            s += v; s2 += v * v;
        }
        mu  = s * (1.0f / FL);
        var = fmaxf(s2 - (float)FL * mu * mu, 0.f);
        muX[col]  = mu;
        invX[col] = 1.f / (sqrtf(var) + EPSF);
    }
    __syncthreads();

    const int warp = tid >> 5, lane = tid & 31;
    float acc = 0.f;
    for (int t = warp; t < FL; t += 8) {
        float aU = 0.f, aV = 0.f, a2U = 0.f, a2V = 0.f, aUV = 0.f;
        for (int c = lane; c < FEAT; c += 32) {
            float u = sS[t * FEAT + c];
            float v = (X[t * FEAT + c] - muX[c]) * invX[c];
            aU += u; aV += v; a2U += u * u; a2V += v * v; aUV += u * v;
        }
#pragma unroll
        for (int o = 16; o > 0; o >>= 1) {
            aU  += __shfl_down_sync(0xffffffffu, aU,  o);
            aV  += __shfl_down_sync(0xffffffffu, aV,  o);
            a2U += __shfl_down_sync(0xffffffffu, a2U, o);
            a2V += __shfl_down_sync(0xffffffffu, a2V, o);
            aUV += __shfl_down_sync(0xffffffffu, aUV, o);
        }
        if (lane == 0) {
            float muU = aU * (1.0f / FEAT), muV = aV * (1.0f / FEAT);
            float sgU = sqrtf(fmaxf(a2U - (float)FEAT * muU * muU, 0.f));
            float sgV = sqrtf(fmaxf(a2V - (float)FEAT * muV * muV, 0.f));
            float dot = aUV - (float)FEAT * muU * muV;
            acc += dot / ((sgU + EPSF) * (sgV + EPSF));
        }
    }
    if (lane == 0) red[warp] = acc;
    __syncthreads();
    if (tid == 0) {
        float tot = 0.f;
#pragma unroll
        for (int i = 0; i < 8; i++) tot += red[i];
        atomicAdd(&out[b], tot * (1.0f / ((float)FL * (float)NFR)));
    }
}

__global__ void zero_out(float* out, int n)
{
    int i = blockIdx.x * blockDim.x + threadIdx.x;
    if (i < n) out[i] = 0.f;
}

extern "C" void kernel_launch(void* const* d_in, const int* in_sizes, int n_in,
                              void* d_out, int out_size)
{
    const float* s  = (const float*)d_in[0];
    const float* x  = (const float*)d_in[1];
    const float* w0 = (const float*)d_in[2];
    const float* b0 = (const float*)d_in[3];
    const float* w1 = (const float*)d_in[4];
    const float* b1 = (const float*)d_in[5];
    const float* w2 = (const float*)d_in[6];
    const float* b2 = (const float*)d_in[7];
    float* out = (float*)d_out;

    // D2D copies into constant memory (graph-capturable memcpy nodes).
    cudaMemcpyToSymbolAsync(CW0, w0, 9 * 1  * K_ * sizeof(float), 0, cudaMemcpyDeviceToDevice, 0);
    cudaMemcpyToSymbolAsync(CB0, b0, K_ * sizeof(float),          0, cudaMemcpyDeviceToDevice, 0);
    cudaMemcpyToSymbolAsync(CW1, w1, 9 * K_ * K_ * sizeof(float), 0, cudaMemcpyDeviceToDevice, 0);
    cudaMemcpyToSymbolAsync(CB1, b1, K_ * sizeof(float),          0, cudaMemcpyDeviceToDevice, 0);
    cudaMemcpyToSymbolAsync(CW2, w2, 9 * K_ * K_ * sizeof(float), 0, cudaMemcpyDeviceToDevice, 0);
    cudaMemcpyToSymbolAsync(CB2, b2, K_ * sizeof(float),          0, cudaMemcpyDeviceToDevice, 0);

    zero_out<<<1, 32>>>(out, out_size);

    dim3 cgrid(T_ / TB, 2 * B_);
    conv_kernel<1,  true,  0, 0, 0><<<cgrid, 256>>>(s, x);            // -> bufA
    conv_kernel<K_, false, 0, 1, 1><<<cgrid, 256>>>(nullptr, nullptr); // A -> B
    conv_kernel<K_, false, 1, 0, 2><<<cgrid, 256>>>(nullptr, nullptr); // B -> A

    dim3 ggrid(NFR, B_);
    corr_kernel<<<ggrid, 256>>>(out);
}

// round 7
// speedup vs baseline: 1.3533x; 1.1806x over previous
#include <cuda_runtime.h>
#include <math.h>

#define B_   16
#define T_   512
#define F_   17
#define K_   20
#define FEAT (F_*K_)        // 340
#define FL   30
#define NFR  (T_ - FL + 1)  // 483
#define TB   30             // 30*17 = 510 positions ~= 2*256 thread-slots
#define NTBLK ((T_ + TB - 1) / TB)   // 18
#define EPSF 1e-12f

// Scratch: ping-pong activation buffers for both towers stacked as 32 "batches".
__device__ float g_bufA[2 * B_ * T_ * F_ * K_];
__device__ float g_bufB[2 * B_ * T_ * F_ * K_];

// Weights/biases in constant memory (warp-uniform -> LDC port, no L1TEX).
__constant__ __align__(16) float CW0[9 * 1  * K_];
__constant__ __align__(16) float CW1[9 * K_ * K_];
__constant__ __align__(16) float CW2[9 * K_ * K_];
__constant__ float CB0[K_];
__constant__ float CB1[K_];
__constant__ float CB2[K_];

// ---------------------------------------------------------------------------
// Conv 3x3 SAME + bias + ReLU. NHWC activations, weights in constant.
// CTA = (t-block of TB=30 rows) x (one of 32 tower-batches). 256 threads.
// Each thread: 2 positions x 20 output channels; 510 of 512 slots useful.
// Grid = 18*32 = 576 CTAs = one full wave at 4 CTAs/SM.
// ---------------------------------------------------------------------------
template<int CIN, bool FIRST, int SRC, int DST, int LAYER>
__global__ void __launch_bounds__(256) conv_kernel(
    const float* __restrict__ in0, const float* __restrict__ in1)
{
    constexpr int CINP = (CIN % 2 == 0) ? CIN + 1 : CIN;   // 21 for 20, 1 for 1

    extern __shared__ float tile[];   // (TB+2) * (F_+2) * CINP floats

    const int tid = threadIdx.x;
    const int t0  = blockIdx.x * TB;
    const int bb  = blockIdx.y;   // 0..31 (0..15 = S tower, 16..31 = X tower)

    const float* src;
    if (FIRST) {
        src = (bb < B_) ? (in0 + (size_t)bb * T_ * F_)
                        : (in1 + (size_t)(bb - B_) * T_ * F_);
    } else {
        const float* base = (SRC == 0) ? g_bufA : g_bufB;
        src = base + (size_t)bb * T_ * F_ * CIN;
    }
    float* dst = ((DST == 0) ? g_bufA : g_bufB);

    const int tileN = (TB + 2) * (F_ + 2) * CIN;   // logical elements
    for (int i = tid; i < tileN; i += 256) {
        int cin  = i % CIN;
        int rest = i / CIN;
        int ff   = rest % (F_ + 2);
        int tt   = rest / (F_ + 2);
        int t = t0 - 1 + tt;
        int f = ff - 1;
        float v = 0.f;
        if (t >= 0 && t < T_ && f >= 0 && f < F_)
            v = src[((size_t)t * F_ + f) * CIN + cin];
        tile[(tt * (F_ + 2) + ff) * CINP + cin] = v;
    }
    __syncthreads();

    float acc0[K_], acc1[K_];
#pragma unroll
    for (int k = 0; k < K_; k++) {
        float bk;
        if constexpr (LAYER == 0) bk = CB0[k];
        else if constexpr (LAYER == 1) bk = CB1[k];
        else bk = CB2[k];
        acc0[k] = bk; acc1[k] = bk;
    }

    const bool ok0 = (tid < TB * F_);                  // always true (256 < 510)
    const bool ok1 = (tid + 256 < TB * F_);            // 254 of 256 threads
    const int pos0 = ok0 ? tid : 0;
    const int pos1 = ok1 ? (tid + 256) : 0;            // clamp keeps smem idx legal
    const int lt0 = pos0 / F_, lf0 = pos0 % F_;
    const int lt1 = pos1 / F_, lf1 = pos1 % F_;

    for (int cin = 0; cin < CIN; cin++) {
#pragma unroll
        for (int dt = 0; dt < 3; dt++) {
#pragma unroll
            for (int df = 0; df < 3; df++) {
                const int wbase = ((dt * 3 + df) * CIN + cin) * K_;  // 80B-aligned
                float i0 = tile[((lt0 + dt) * (F_ + 2) + lf0 + df) * CINP + cin];
                float i1 = tile[((lt1 + dt) * (F_ + 2) + lf1 + df) * CINP + cin];
#pragma unroll
                for (int q = 0; q < 5; q++) {
                    float4 wv;
                    if constexpr (LAYER == 0)
                        wv = reinterpret_cast<const float4*>(CW0 + wbase)[q];
                    else if constexpr (LAYER == 1)
                        wv = reinterpret_cast<const float4*>(CW1 + wbase)[q];
                    else
                        wv = reinterpret_cast<const float4*>(CW2 + wbase)[q];
                    acc0[4*q+0] = fmaf(i0, wv.x, acc0[4*q+0]);
                    acc0[4*q+1] = fmaf(i0, wv.y, acc0[4*q+1]);
                    acc0[4*q+2] = fmaf(i0, wv.z, acc0[4*q+2]);
                    acc0[4*q+3] = fmaf(i0, wv.w, acc0[4*q+3]);
                    acc1[4*q+0] = fmaf(i1, wv.x, acc1[4*q+0]);
                    acc1[4*q+1] = fmaf(i1, wv.y, acc1[4*q+1]);
                    acc1[4*q+2] = fmaf(i1, wv.z, acc1[4*q+2]);
                    acc1[4*q+3] = fmaf(i1, wv.w, acc1[4*q+3]);
                }
            }
        }
    }

    if (ok0 && (t0 + lt0) < T_) {
        int t = t0 + lt0;
        float* o = dst + (((size_t)bb * T_ + t) * F_ + lf0) * K_;
#pragma unroll
        for (int k = 0; k < K_; k++) o[k] = fmaxf(acc0[k], 0.f);
    }
    if (ok1 && (t0 + lt1) < T_) {
        int t = t0 + lt1;
        float* o = dst + (((size_t)bb * T_ + t) * F_ + lf1) * K_;
#pragma unroll
        for (int k = 0; k < K_; k++) o[k] = fmaxf(acc1[k], 0.f);
    }
}

// ---------------------------------------------------------------------------
// Per-frame double-normalized cross-correlation (unchanged).
// ---------------------------------------------------------------------------
__global__ void __launch_bounds__(256) corr_kernel(float* __restrict__ out)
{
    __shared__ float sS[FL * FEAT];        // 40800 B
    __shared__ float muX[FEAT], invX[FEAT];
    __shared__ float red[8];

    const int fr  = blockIdx.x;   // 0..482
    const int b   = blockIdx.y;   // 0..15
    const int tid = threadIdx.x;

    const float* S = g_bufA + ((size_t)b * T_ + fr) * FEAT;
    const float* X = g_bufA + ((size_t)(b + B_) * T_ + fr) * FEAT;

    for (int i = tid; i < FL * FEAT; i += 256) sS[i] = S[i];
    __syncthreads();

    for (int col = tid; col < FEAT; col += 256) {
        float s = 0.f, s2 = 0.f;
#pragma unroll 6
        for (int t = 0; t < FL; t++) {
            float v = sS[t * FEAT + col];
            s += v; s2 += v * v;
        }
        float mu  = s * (1.0f / FL);
        float var = fmaxf(s2 - (float)FL * mu * mu, 0.f);
        float inv = 1.f / (sqrtf(var) + EPSF);
#pragma unroll 6
        for (int t = 0; t < FL; t++)
            sS[t * FEAT + col] = (sS[t * FEAT + col] - mu) * inv;

        s = 0.f; s2 = 0.f;
#pragma unroll 6
        for (int t = 0; t < FL; t++) {
            float v = X[t * FEAT + col];     // coalesced across threads
            s += v; s2 += v * v;
        }
        mu  = s * (1.0f / FL);
        var = fmaxf(s2 - (float)FL * mu * mu, 0.f);
        muX[col]  = mu;
        invX[col] = 1.f / (sqrtf(var) + EPSF);
    }
    __syncthreads();

    const int warp = tid >> 5, lane = tid & 31;
    float acc = 0.f;
    for (int t = warp; t < FL; t += 8) {
        float aU = 0.f, aV = 0.f, a2U = 0.f, a2V = 0.f, aUV = 0.f;
        for (int c = lane; c < FEAT; c += 32) {
            float u = sS[t * FEAT + c];
            float v = (X[t * FEAT + c] - muX[c]) * invX[c];
            aU += u; aV += v; a2U += u * u; a2V += v * v; aUV += u * v;
        }
#pragma unroll
        for (int o = 16; o > 0; o >>= 1) {
            aU  += __shfl_down_sync(0xffffffffu, aU,  o);
            aV  += __shfl_down_sync(0xffffffffu, aV,  o);
            a2U += __shfl_down_sync(0xffffffffu, a2U, o);
            a2V += __shfl_down_sync(0xffffffffu, a2V, o);
            aUV += __shfl_down_sync(0xffffffffu, aUV, o);
        }
        if (lane == 0) {
            float muU = aU * (1.0f / FEAT), muV = aV * (1.0f / FEAT);
            float sgU = sqrtf(fmaxf(a2U - (float)FEAT * muU * muU, 0.f));
            float sgV = sqrtf(fmaxf(a2V - (float)FEAT * muV * muV, 0.f));
            float dot = aUV - (float)FEAT * muU * muV;
            acc += dot / ((sgU + EPSF) * (sgV + EPSF));
        }
    }
    if (lane == 0) red[warp] = acc;
    __syncthreads();
    if (tid == 0) {
        float tot = 0.f;
#pragma unroll
        for (int i = 0; i < 8; i++) tot += red[i];
        atomicAdd(&out[b], tot * (1.0f / ((float)FL * (float)NFR)));
    }
}

__global__ void zero_out(float* out, int n)
{
    int i = blockIdx.x * blockDim.x + threadIdx.x;
    if (i < n) out[i] = 0.f;
}

extern "C" void kernel_launch(void* const* d_in, const int* in_sizes, int n_in,
                              void* d_out, int out_size)
{
    const float* s  = (const float*)d_in[0];
    const float* x  = (const float*)d_in[1];
    const float* w0 = (const float*)d_in[2];
    const float* b0 = (const float*)d_in[3];
    const float* w1 = (const float*)d_in[4];
    const float* b1 = (const float*)d_in[5];
    const float* w2 = (const float*)d_in[6];
    const float* b2 = (const float*)d_in[7];
    float* out = (float*)d_out;

    // D2D copies into constant memory (graph-capturable memcpy nodes).
    cudaMemcpyToSymbolAsync(CW0, w0, 9 * 1  * K_ * sizeof(float), 0, cudaMemcpyDeviceToDevice, 0);
    cudaMemcpyToSymbolAsync(CB0, b0, K_ * sizeof(float),          0, cudaMemcpyDeviceToDevice, 0);
    cudaMemcpyToSymbolAsync(CW1, w1, 9 * K_ * K_ * sizeof(float), 0, cudaMemcpyDeviceToDevice, 0);
    cudaMemcpyToSymbolAsync(CB1, b1, K_ * sizeof(float),          0, cudaMemcpyDeviceToDevice, 0);
    cudaMemcpyToSymbolAsync(CW2, w2, 9 * K_ * K_ * sizeof(float), 0, cudaMemcpyDeviceToDevice, 0);
    cudaMemcpyToSymbolAsync(CB2, b2, K_ * sizeof(float),          0, cudaMemcpyDeviceToDevice, 0);

    zero_out<<<1, 32>>>(out, out_size);

    // Dynamic smem sizes
    const int smem1  = (TB + 2) * (F_ + 2) * 1  * (int)sizeof(float);  //  2432 B
    const int smem20 = (TB + 2) * (F_ + 2) * 21 * (int)sizeof(float);  // 51072 B

    // Opt-in >48KB dynamic smem for the CIN=20 instantiations (non-stream
    // attribute calls; graph-capture legal, idempotent).
    cudaFuncSetAttribute(conv_kernel<K_, false, 0, 1, 1>,
                         cudaFuncAttributeMaxDynamicSharedMemorySize, smem20);
    cudaFuncSetAttribute(conv_kernel<K_, false, 1, 0, 2>,
                         cudaFuncAttributeMaxDynamicSharedMemorySize, smem20);

    dim3 cgrid(NTBLK, 2 * B_);   // 18 x 32 = 576 CTAs
    conv_kernel<1,  true,  0, 0, 0><<<cgrid, 256, smem1 >>>(s, x);             // -> bufA
    conv_kernel<K_, false, 0, 1, 1><<<cgrid, 256, smem20>>>(nullptr, nullptr); // A -> B
    conv_kernel<K_, false, 1, 0, 2><<<cgrid, 256, smem20>>>(nullptr, nullptr); // B -> A

    dim3 ggrid(NFR, B_);
    corr_kernel<<<ggrid, 256>>>(out);
}